// round 1
// baseline (speedup 1.0000x reference)
#include <cuda_runtime.h>
#include <cuda_bf16.h>
#include <cstddef>

#define NODES_MAX 100000
#define DD 128

// Scratch buffers (static device globals: allowed; no runtime allocation)
__device__ float g_bufA[(size_t)NODES_MAX * DD];
__device__ float g_bufB[(size_t)NODES_MAX * DD];
__device__ float g_bufC[(size_t)NODES_MAX * DD];
__device__ float g_bufD[(size_t)NODES_MAX * DD];
__device__ float g_stats[2 * DD];
__device__ float g_scale[DD];
__device__ float g_shift[DD];

// ---------------------------------------------------------------------------
// GEMM: C[M,128] = A[M,128] @ B[128,128] (+bias, optional relu)
// BM=64, BN=128 (full), BK=64, 256 threads, thread tile 4x8
// ---------------------------------------------------------------------------
__global__ __launch_bounds__(256) void gemm_kernel(
    const float* __restrict__ A, const float* __restrict__ B,
    const float* __restrict__ bias, float* __restrict__ C,
    int M, int do_relu)
{
    __shared__ float As[64][68];   // padded row stride (68 % 4 == 0 keeps float4 align)
    __shared__ float Bs[64][128];

    const int tid = threadIdx.x;
    const int tx = tid & 15;   // n-group: cols [tx*8, tx*8+8)
    const int ty = tid >> 4;   // m-group: rows [ty*4, ty*4+4)
    const int m0 = blockIdx.x * 64;

    float acc[4][8];
#pragma unroll
    for (int i = 0; i < 4; i++)
#pragma unroll
        for (int j = 0; j < 8; j++) acc[i][j] = 0.f;

    for (int k0 = 0; k0 < 128; k0 += 64) {
        // Load A tile 64x64 (4 float4 per thread)
#pragma unroll
        for (int i = 0; i < 4; i++) {
            int f = tid + i * 256;
            int r = f >> 4;
            int c = (f & 15) << 2;
            int gr = m0 + r;
            float4 v = make_float4(0.f, 0.f, 0.f, 0.f);
            if (gr < M) v = *(const float4*)(A + (size_t)gr * 128 + k0 + c);
            *(float4*)&As[r][c] = v;
        }
        // Load B tile 64x128 (8 float4 per thread)
#pragma unroll
        for (int i = 0; i < 8; i++) {
            int f = tid + i * 256;
            int r = f >> 5;
            int c = (f & 31) << 2;
            *(float4*)&Bs[r][c] = *(const float4*)(B + (size_t)(k0 + r) * 128 + c);
        }
        __syncthreads();

#pragma unroll
        for (int k = 0; k < 64; k += 4) {
            float4 a4[4];
#pragma unroll
            for (int i = 0; i < 4; i++)
                a4[i] = *(const float4*)&As[ty * 4 + i][k];
#pragma unroll
            for (int kk = 0; kk < 4; kk++) {
                float4 b0 = *(const float4*)&Bs[k + kk][tx * 8];
                float4 b1 = *(const float4*)&Bs[k + kk][tx * 8 + 4];
#pragma unroll
                for (int i = 0; i < 4; i++) {
                    float a = (kk == 0) ? a4[i].x : (kk == 1) ? a4[i].y
                              : (kk == 2) ? a4[i].z : a4[i].w;
                    acc[i][0] += a * b0.x;
                    acc[i][1] += a * b0.y;
                    acc[i][2] += a * b0.z;
                    acc[i][3] += a * b0.w;
                    acc[i][4] += a * b1.x;
                    acc[i][5] += a * b1.y;
                    acc[i][6] += a * b1.z;
                    acc[i][7] += a * b1.w;
                }
            }
        }
        __syncthreads();
    }

    float bb[8];
    if (bias) {
        float4 t0 = *(const float4*)(bias + tx * 8);
        float4 t1 = *(const float4*)(bias + tx * 8 + 4);
        bb[0] = t0.x; bb[1] = t0.y; bb[2] = t0.z; bb[3] = t0.w;
        bb[4] = t1.x; bb[5] = t1.y; bb[6] = t1.z; bb[7] = t1.w;
    } else {
#pragma unroll
        for (int j = 0; j < 8; j++) bb[j] = 0.f;
    }

#pragma unroll
    for (int i = 0; i < 4; i++) {
        int gr = m0 + ty * 4 + i;
        if (gr < M) {
            float o[8];
#pragma unroll
            for (int j = 0; j < 8; j++) {
                float v = acc[i][j] + bb[j];
                o[j] = do_relu ? fmaxf(v, 0.f) : v;
            }
            *(float4*)(C + (size_t)gr * 128 + tx * 8)     = make_float4(o[0], o[1], o[2], o[3]);
            *(float4*)(C + (size_t)gr * 128 + tx * 8 + 4) = make_float4(o[4], o[5], o[6], o[7]);
        }
    }
}

// ---------------------------------------------------------------------------
// Edge scatter: agg[dst[e]] += m[src[e]], one warp per edge, red.v4.f32
// ---------------------------------------------------------------------------
__global__ __launch_bounds__(256) void scatter_kernel(
    const float* __restrict__ m, const int* __restrict__ src,
    const int* __restrict__ dst, float* __restrict__ agg, int E)
{
    int w = (int)((blockIdx.x * (unsigned)blockDim.x + threadIdx.x) >> 5);
    int lane = threadIdx.x & 31;
    if (w >= E) return;
    int s = __ldg(src + w);
    int d = __ldg(dst + w);
    float4 v = *(const float4*)(m + (size_t)s * 128 + lane * 4);
    float* p = agg + (size_t)d * 128 + lane * 4;
    asm volatile("red.global.add.v4.f32 [%0], {%1, %2, %3, %4};"
                 :: "l"(p), "f"(v.x), "f"(v.y), "f"(v.z), "f"(v.w)
                 : "memory");
}

// ---------------------------------------------------------------------------
// Combine: out = relu(agg + b) + res; accumulate per-column sum and sumsq
// ---------------------------------------------------------------------------
__global__ __launch_bounds__(256) void combine_kernel(
    const float* __restrict__ agg, const float* __restrict__ res,
    const float* __restrict__ bias, float* __restrict__ out,
    float* __restrict__ stats, int M)
{
    const int c4 = threadIdx.x & 31;   // float4 column group
    const int rl = threadIdx.x >> 5;   // 0..7 row lane

    float4 b = ((const float4*)bias)[c4];
    float4 s = make_float4(0.f, 0.f, 0.f, 0.f);
    float4 q = make_float4(0.f, 0.f, 0.f, 0.f);

    for (int r = blockIdx.x * 8 + rl; r < M; r += gridDim.x * 8) {
        float4 a  = ((const float4*)(agg + (size_t)r * 128))[c4];
        float4 rr = ((const float4*)(res + (size_t)r * 128))[c4];
        float4 v;
        v.x = fmaxf(a.x + b.x, 0.f) + rr.x;
        v.y = fmaxf(a.y + b.y, 0.f) + rr.y;
        v.z = fmaxf(a.z + b.z, 0.f) + rr.z;
        v.w = fmaxf(a.w + b.w, 0.f) + rr.w;
        ((float4*)(out + (size_t)r * 128))[c4] = v;
        s.x += v.x; s.y += v.y; s.z += v.z; s.w += v.w;
        q.x += v.x * v.x; q.y += v.y * v.y; q.z += v.z * v.z; q.w += v.w * v.w;
    }

    __shared__ float4 sh[8][32];
    __shared__ float4 shq[8][32];
    sh[rl][c4] = s;
    shq[rl][c4] = q;
    __syncthreads();

    if (rl == 0) {
#pragma unroll
        for (int j = 1; j < 8; j++) {
            float4 t = sh[j][c4];
            s.x += t.x; s.y += t.y; s.z += t.z; s.w += t.w;
            float4 u = shq[j][c4];
            q.x += u.x; q.y += u.y; q.z += u.z; q.w += u.w;
        }
        atomicAdd(&stats[c4 * 4 + 0], s.x);
        atomicAdd(&stats[c4 * 4 + 1], s.y);
        atomicAdd(&stats[c4 * 4 + 2], s.z);
        atomicAdd(&stats[c4 * 4 + 3], s.w);
        atomicAdd(&stats[128 + c4 * 4 + 0], q.x);
        atomicAdd(&stats[128 + c4 * 4 + 1], q.y);
        atomicAdd(&stats[128 + c4 * 4 + 2], q.z);
        atomicAdd(&stats[128 + c4 * 4 + 3], q.w);
    }
}

// ---------------------------------------------------------------------------
// Finalize BN: scale = rsqrt(var+eps)*gamma, shift = beta - mean*scale
// ---------------------------------------------------------------------------
__global__ void finalize_kernel(const float* __restrict__ stats,
                                const float* __restrict__ g,
                                const float* __restrict__ be,
                                float invN,
                                float* __restrict__ scale,
                                float* __restrict__ shift)
{
    int j = threadIdx.x;
    float mu = stats[j] * invN;
    float var = stats[128 + j] * invN - mu * mu;
    float sc = rsqrtf(var + 1e-5f) * g[j];
    scale[j] = sc;
    shift[j] = be[j] - mu * sc;
}

// ---------------------------------------------------------------------------
// Normalize: y = x * scale[col] + shift[col]
// ---------------------------------------------------------------------------
__global__ __launch_bounds__(256) void normalize_kernel(
    const float* __restrict__ x, const float* __restrict__ scale,
    const float* __restrict__ shift, float* __restrict__ y, int M)
{
    int total = M * 32;  // float4 count
    for (int idx = blockIdx.x * blockDim.x + threadIdx.x; idx < total;
         idx += gridDim.x * blockDim.x) {
        int c4 = idx & 31;
        float4 sc = ((const float4*)scale)[c4];
        float4 sf = ((const float4*)shift)[c4];
        float4 v = ((const float4*)x)[idx];
        v.x = v.x * sc.x + sf.x;
        v.y = v.y * sc.y + sf.y;
        v.z = v.z * sc.z + sf.z;
        v.w = v.w * sc.w + sf.w;
        ((float4*)y)[idx] = v;
    }
}

// ---------------------------------------------------------------------------
extern "C" void kernel_launch(void* const* d_in, const int* in_sizes, int n_in,
                              void* d_out, int out_size)
{
    const float* h   = (const float*)d_in[0];
    const int*   src = (const int*)d_in[1];
    const int*   dst = (const int*)d_in[2];
    const float* W0  = (const float*)d_in[3];
    const float* b0  = (const float*)d_in[4];
    const float* Wr0 = (const float*)d_in[5];
    const float* br0 = (const float*)d_in[6];
    const float* g0  = (const float*)d_in[7];
    const float* be0 = (const float*)d_in[8];
    const float* W1  = (const float*)d_in[9];
    const float* b1  = (const float*)d_in[10];
    const float* Wr1 = (const float*)d_in[11];
    const float* br1 = (const float*)d_in[12];
    const float* g1  = (const float*)d_in[13];
    const float* be1 = (const float*)d_in[14];

    const int M = in_sizes[0] / 128;
    const int E = in_sizes[1];

    float *A, *B, *C, *Dd, *stats, *scale, *shift;
    cudaGetSymbolAddress((void**)&A,     g_bufA);
    cudaGetSymbolAddress((void**)&B,     g_bufB);
    cudaGetSymbolAddress((void**)&C,     g_bufC);
    cudaGetSymbolAddress((void**)&Dd,    g_bufD);
    cudaGetSymbolAddress((void**)&stats, g_stats);
    cudaGetSymbolAddress((void**)&scale, g_scale);
    cudaGetSymbolAddress((void**)&shift, g_shift);

    const int gBlocks = (M + 63) / 64;
    const int sBlocks = (E + 7) / 8;           // 8 warps per block, 1 edge/warp
    const size_t bytes = (size_t)M * 128 * sizeof(float);
    float* out = (float*)d_out;

    // ---- Layer 1 ----
    gemm_kernel<<<gBlocks, 256>>>(h, W0, nullptr, A, M, 0);     // m1 = h@W0
    gemm_kernel<<<gBlocks, 256>>>(h, Wr0, br0, B, M, 1);        // res1 = relu(h@Wr0+br0)
    cudaMemsetAsync(C, 0, bytes);
    scatter_kernel<<<sBlocks, 256>>>(A, src, dst, C, E);        // agg1
    cudaMemsetAsync(stats, 0, 256 * sizeof(float));
    combine_kernel<<<1024, 256>>>(C, B, b0, A, stats, M);       // out1 -> A (+stats)
    finalize_kernel<<<1, 128>>>(stats, g0, be0, 1.0f / (float)M, scale, shift);
    normalize_kernel<<<1024, 256>>>(A, scale, shift, B, M);     // x1 -> B

    // ---- Layer 2 ----
    gemm_kernel<<<gBlocks, 256>>>(B, W1, nullptr, A, M, 0);     // m2 = x1@W1
    gemm_kernel<<<gBlocks, 256>>>(B, Wr1, br1, Dd, M, 1);       // res2
    cudaMemsetAsync(C, 0, bytes);
    scatter_kernel<<<sBlocks, 256>>>(A, src, dst, C, E);        // agg2
    cudaMemsetAsync(stats, 0, 256 * sizeof(float));
    combine_kernel<<<1024, 256>>>(C, Dd, b1, A, stats, M);      // out2 -> A (+stats)
    finalize_kernel<<<1, 128>>>(stats, g1, be1, 1.0f / (float)M, scale, shift);
    normalize_kernel<<<1024, 256>>>(A, scale, shift, out, M);   // final -> d_out
}

// round 2
// speedup vs baseline: 1.4063x; 1.4063x over previous
#include <cuda_runtime.h>
#include <cuda_bf16.h>
#include <cstddef>

#define NODES_MAX 100000
#define EDGES_MAX 1600000
#define DD 128

// ---------------------------------------------------------------------------
// Static device scratch (no runtime allocation allowed)
// ---------------------------------------------------------------------------
__device__ float g_bufA[(size_t)NODES_MAX * DD];   // m (x @ W)
__device__ float g_bufB[(size_t)NODES_MAX * DD];   // res
__device__ float g_bufC[(size_t)NODES_MAX * DD];   // y1 (layer1 pre-norm output)
__device__ float g_bufD[(size_t)NODES_MAX * DD];   // y2
__device__ float g_stats[2 * DD];
__device__ float g_scale[DD];
__device__ float g_shift[DD];
__device__ float g_W1p[DD * DD];
__device__ float g_Wr1p[DD * DD];
__device__ float g_c0[DD];
__device__ float g_br1p[DD];
__device__ int   g_rowptr[NODES_MAX + 1];
__device__ int   g_cursor[NODES_MAX];   // also used as deg histogram
__device__ int   g_esrc[EDGES_MAX];
__device__ int   g_bsum[128];

// ---------------------------------------------------------------------------
// f32x2 packed helpers (FFMA2 — sm_100+)
// ---------------------------------------------------------------------------
__device__ __forceinline__ unsigned long long pack2(float a) {
    unsigned long long r;
    asm("mov.b64 %0, {%1, %1};" : "=l"(r) : "f"(a));
    return r;
}
__device__ __forceinline__ float2 unpack2(unsigned long long v) {
    float2 f;
    asm("mov.b64 {%0, %1}, %2;" : "=f"(f.x), "=f"(f.y) : "l"(v));
    return f;
}
__device__ __forceinline__ void fma2(unsigned long long& d,
                                     unsigned long long a,
                                     unsigned long long b) {
    asm("fma.rn.f32x2 %0, %1, %2, %0;" : "+l"(d) : "l"(a), "l"(b));
}

// ---------------------------------------------------------------------------
// GEMM: C[M,128] = A[M,128] @ B[128,128] (+bias, optional relu)
// BM=128, BN=128, BK=32, 256 threads, thread tile 8x8, f32x2 accumulators
// ---------------------------------------------------------------------------
__global__ __launch_bounds__(256) void gemm_kernel(
    const float* __restrict__ A, const float* __restrict__ B,
    const float* __restrict__ bias, float* __restrict__ C,
    int M, int do_relu)
{
    __shared__ float As[128][36];  // pad to 36 (36 % 4 == 0 keeps float4 align)
    __shared__ float Bs[32][128];

    const int tid = threadIdx.x;
    const int tx = tid & 15;       // cols [tx*8, tx*8+8)
    const int ty = tid >> 4;       // rows [ty*8, ty*8+8)
    const int m0 = blockIdx.x * 128;

    unsigned long long acc[8][4];
#pragma unroll
    for (int i = 0; i < 8; i++)
#pragma unroll
        for (int j = 0; j < 4; j++) acc[i][j] = 0ull;

    for (int k0 = 0; k0 < 128; k0 += 32) {
        // Load A tile 128x32 (4 float4 per thread)
#pragma unroll
        for (int i = 0; i < 4; i++) {
            int f = tid + i * 256;
            int r = f >> 3;
            int c = (f & 7) << 2;
            int gr = m0 + r;
            float4 v = make_float4(0.f, 0.f, 0.f, 0.f);
            if (gr < M) v = *(const float4*)(A + (size_t)gr * 128 + k0 + c);
            *(float4*)&As[r][c] = v;
        }
        // Load B tile 32x128 (4 float4 per thread)
#pragma unroll
        for (int i = 0; i < 4; i++) {
            int f = tid + i * 256;
            int r = f >> 5;
            int c = (f & 31) << 2;
            *(float4*)&Bs[r][c] = *(const float4*)(B + (size_t)(k0 + r) * 128 + c);
        }
        __syncthreads();

#pragma unroll
        for (int k4 = 0; k4 < 32; k4 += 4) {
            float4 a4[8];
#pragma unroll
            for (int i = 0; i < 8; i++)
                a4[i] = *(const float4*)&As[ty * 8 + i][k4];
#pragma unroll
            for (int kk = 0; kk < 4; kk++) {
                const unsigned long long* bp =
                    (const unsigned long long*)&Bs[k4 + kk][tx * 8];
                unsigned long long b0 = bp[0], b1 = bp[1], b2 = bp[2], b3 = bp[3];
#pragma unroll
                for (int i = 0; i < 8; i++) {
                    float a = (kk == 0) ? a4[i].x : (kk == 1) ? a4[i].y
                              : (kk == 2) ? a4[i].z : a4[i].w;
                    unsigned long long ap = pack2(a);
                    fma2(acc[i][0], ap, b0);
                    fma2(acc[i][1], ap, b1);
                    fma2(acc[i][2], ap, b2);
                    fma2(acc[i][3], ap, b3);
                }
            }
        }
        __syncthreads();
    }

    float bb[8];
    if (bias) {
        float4 t0 = *(const float4*)(bias + tx * 8);
        float4 t1 = *(const float4*)(bias + tx * 8 + 4);
        bb[0] = t0.x; bb[1] = t0.y; bb[2] = t0.z; bb[3] = t0.w;
        bb[4] = t1.x; bb[5] = t1.y; bb[6] = t1.z; bb[7] = t1.w;
    } else {
#pragma unroll
        for (int j = 0; j < 8; j++) bb[j] = 0.f;
    }

#pragma unroll
    for (int i = 0; i < 8; i++) {
        int gr = m0 + ty * 8 + i;
        if (gr < M) {
            float o[8];
#pragma unroll
            for (int j = 0; j < 4; j++) {
                float2 f = unpack2(acc[i][j]);
                float v0 = f.x + bb[j * 2];
                float v1 = f.y + bb[j * 2 + 1];
                o[j * 2]     = do_relu ? fmaxf(v0, 0.f) : v0;
                o[j * 2 + 1] = do_relu ? fmaxf(v1, 0.f) : v1;
            }
            *(float4*)(C + (size_t)gr * 128 + tx * 8)     = make_float4(o[0], o[1], o[2], o[3]);
            *(float4*)(C + (size_t)gr * 128 + tx * 8 + 4) = make_float4(o[4], o[5], o[6], o[7]);
        }
    }
}

// ---------------------------------------------------------------------------
// CSR build: histogram -> 2-level exclusive scan -> fill
// ---------------------------------------------------------------------------
__global__ void hist_kernel(const int* __restrict__ dst, int* __restrict__ deg, int E)
{
    int i = blockIdx.x * blockDim.x + threadIdx.x;
    if (i < E) atomicAdd(&deg[dst[i]], 1);
}

__global__ void scan1_kernel(const int* __restrict__ deg, int* __restrict__ rowptr,
                             int* __restrict__ bsum, int N)
{
    __shared__ int ws[8];
    int tid = threadIdx.x;
    int base = blockIdx.x * 2048 + tid * 8;
    int v[8];
    int run = 0;
#pragma unroll
    for (int i = 0; i < 8; i++) {
        int t = (base + i < N) ? deg[base + i] : 0;
        v[i] = run;
        run += t;
    }
    int lane = tid & 31, wid = tid >> 5;
    int x = run;
#pragma unroll
    for (int o = 1; o < 32; o <<= 1) {
        int y = __shfl_up_sync(0xffffffffu, x, o);
        if (lane >= o) x += y;
    }
    if (lane == 31) ws[wid] = x;
    __syncthreads();
    if (tid == 0) {
        int acc = 0;
#pragma unroll
        for (int j = 0; j < 8; j++) { int t = ws[j]; ws[j] = acc; acc += t; }
        bsum[blockIdx.x] = acc;
    }
    __syncthreads();
    int excl = x - run + ws[wid];
#pragma unroll
    for (int i = 0; i < 8; i++)
        if (base + i < N) rowptr[base + i] = excl + v[i];
}

__global__ void scan2_kernel(int* __restrict__ bsum, int nb)
{
    if (threadIdx.x == 0) {
        int acc = 0;
        for (int b = 0; b < nb; b++) { int t = bsum[b]; bsum[b] = acc; acc += t; }
    }
}

__global__ void scan3_kernel(int* __restrict__ rowptr, int* __restrict__ cursor,
                             const int* __restrict__ bsum, int N, int E)
{
    int base = blockIdx.x * 2048 + threadIdx.x * 8;
    int off = bsum[blockIdx.x];
#pragma unroll
    for (int k = 0; k < 8; k++) {
        int idx = base + k;
        if (idx < N) {
            int r = rowptr[idx] + off;
            rowptr[idx] = r;
            cursor[idx] = r;
        }
    }
    if (blockIdx.x == 0 && threadIdx.x == 0) rowptr[N] = E;
}

__global__ void fill_kernel(const int* __restrict__ src, const int* __restrict__ dst,
                            int* __restrict__ cursor, int* __restrict__ esrc, int E)
{
    int i = blockIdx.x * blockDim.x + threadIdx.x;
    if (i < E) {
        int p = atomicAdd(&cursor[dst[i]], 1);
        esrc[p] = src[i];
    }
}

// ---------------------------------------------------------------------------
// Fused gather + combine + stats:
// out[n] = relu( sum_{e in CSR[n]} m[esrc[e]] + bias + deg(n)*c0 ) + res[n]
// accumulates per-column sum/sumsq into stats
// ---------------------------------------------------------------------------
__global__ __launch_bounds__(256) void gather_combine_kernel(
    const float* __restrict__ m, const float* __restrict__ res,
    const float* __restrict__ bias, const float* __restrict__ c0,
    const int* __restrict__ rowptr, const int* __restrict__ esrc,
    float* __restrict__ out, float* __restrict__ stats, int M)
{
    const int lane = threadIdx.x & 31;
    const int wid  = threadIdx.x >> 5;
    const int nwarps = (gridDim.x * blockDim.x) >> 5;
    const int w0 = (blockIdx.x * blockDim.x + threadIdx.x) >> 5;

    float4 b4 = ((const float4*)bias)[lane];
    float4 c04 = make_float4(0.f, 0.f, 0.f, 0.f);
    if (c0) c04 = ((const float4*)c0)[lane];

    float4 s = make_float4(0.f, 0.f, 0.f, 0.f);
    float4 q = make_float4(0.f, 0.f, 0.f, 0.f);

    for (int node = w0; node < M; node += nwarps) {
        int start = rowptr[node], end = rowptr[node + 1];
        float4 a0 = make_float4(0.f, 0.f, 0.f, 0.f);
        float4 a1 = make_float4(0.f, 0.f, 0.f, 0.f);
        int e = start;
        for (; e + 1 < end; e += 2) {
            int s0 = __ldg(esrc + e);
            int s1 = __ldg(esrc + e + 1);
            float4 v0 = ((const float4*)(m + (size_t)s0 * 128))[lane];
            float4 v1 = ((const float4*)(m + (size_t)s1 * 128))[lane];
            a0.x += v0.x; a0.y += v0.y; a0.z += v0.z; a0.w += v0.w;
            a1.x += v1.x; a1.y += v1.y; a1.z += v1.z; a1.w += v1.w;
        }
        if (e < end) {
            int s0 = __ldg(esrc + e);
            float4 v0 = ((const float4*)(m + (size_t)s0 * 128))[lane];
            a0.x += v0.x; a0.y += v0.y; a0.z += v0.z; a0.w += v0.w;
        }
        float deg = (float)(end - start);
        float4 rr = ((const float4*)(res + (size_t)node * 128))[lane];
        float4 v;
        v.x = fmaxf(a0.x + a1.x + b4.x + deg * c04.x, 0.f) + rr.x;
        v.y = fmaxf(a0.y + a1.y + b4.y + deg * c04.y, 0.f) + rr.y;
        v.z = fmaxf(a0.z + a1.z + b4.z + deg * c04.z, 0.f) + rr.z;
        v.w = fmaxf(a0.w + a1.w + b4.w + deg * c04.w, 0.f) + rr.w;
        ((float4*)(out + (size_t)node * 128))[lane] = v;
        s.x += v.x; s.y += v.y; s.z += v.z; s.w += v.w;
        q.x += v.x * v.x; q.y += v.y * v.y; q.z += v.z * v.z; q.w += v.w * v.w;
    }

    __shared__ float4 sh[8][32];
    __shared__ float4 shq[8][32];
    sh[wid][lane] = s;
    shq[wid][lane] = q;
    __syncthreads();

    if (wid == 0) {
#pragma unroll
        for (int j = 1; j < 8; j++) {
            float4 t = sh[j][lane];
            s.x += t.x; s.y += t.y; s.z += t.z; s.w += t.w;
            float4 u = shq[j][lane];
            q.x += u.x; q.y += u.y; q.z += u.z; q.w += u.w;
        }
        atomicAdd(&stats[lane * 4 + 0], s.x);
        atomicAdd(&stats[lane * 4 + 1], s.y);
        atomicAdd(&stats[lane * 4 + 2], s.z);
        atomicAdd(&stats[lane * 4 + 3], s.w);
        atomicAdd(&stats[128 + lane * 4 + 0], q.x);
        atomicAdd(&stats[128 + lane * 4 + 1], q.y);
        atomicAdd(&stats[128 + lane * 4 + 2], q.z);
        atomicAdd(&stats[128 + lane * 4 + 3], q.w);
    }
}

// ---------------------------------------------------------------------------
// BN finalize + weight folding
// ---------------------------------------------------------------------------
__global__ void finalize_kernel(const float* __restrict__ stats,
                                const float* __restrict__ g,
                                const float* __restrict__ be,
                                float invN,
                                float* __restrict__ scale,
                                float* __restrict__ shift)
{
    int j = threadIdx.x;
    float mu = stats[j] * invN;
    float var = stats[128 + j] * invN - mu * mu;
    float sc = rsqrtf(var + 1e-5f) * g[j];
    scale[j] = sc;
    shift[j] = be[j] - mu * sc;
}

__global__ void fold_w_kernel(const float* __restrict__ sc,
                              const float* __restrict__ W,
                              float* __restrict__ Wp)
{
    int k = blockIdx.x;
    int j = threadIdx.x;
    Wp[k * 128 + j] = sc[k] * W[k * 128 + j];
}

__global__ void fold_bias_kernel(const float* __restrict__ sf,
                                 const float* __restrict__ W,
                                 const float* __restrict__ baseb,
                                 float* __restrict__ outb)
{
    int j = threadIdx.x;
    float s = baseb ? baseb[j] : 0.f;
    for (int k = 0; k < 128; k++) s += sf[k] * W[k * 128 + j];
    outb[j] = s;
}

// ---------------------------------------------------------------------------
// Normalize: y = x * scale[col] + shift[col]
// ---------------------------------------------------------------------------
__global__ __launch_bounds__(256) void normalize_kernel(
    const float* __restrict__ x, const float* __restrict__ scale,
    const float* __restrict__ shift, float* __restrict__ y, int M)
{
    int total = M * 32;
    for (int idx = blockIdx.x * blockDim.x + threadIdx.x; idx < total;
         idx += gridDim.x * blockDim.x) {
        int c4 = idx & 31;
        float4 sc = ((const float4*)scale)[c4];
        float4 sf = ((const float4*)shift)[c4];
        float4 v = ((const float4*)x)[idx];
        v.x = v.x * sc.x + sf.x;
        v.y = v.y * sc.y + sf.y;
        v.z = v.z * sc.z + sf.z;
        v.w = v.w * sc.w + sf.w;
        ((float4*)y)[idx] = v;
    }
}

// ---------------------------------------------------------------------------
extern "C" void kernel_launch(void* const* d_in, const int* in_sizes, int n_in,
                              void* d_out, int out_size)
{
    const float* h   = (const float*)d_in[0];
    const int*   src = (const int*)d_in[1];
    const int*   dst = (const int*)d_in[2];
    const float* W0  = (const float*)d_in[3];
    const float* b0  = (const float*)d_in[4];
    const float* Wr0 = (const float*)d_in[5];
    const float* br0 = (const float*)d_in[6];
    const float* g0  = (const float*)d_in[7];
    const float* be0 = (const float*)d_in[8];
    const float* W1  = (const float*)d_in[9];
    const float* b1  = (const float*)d_in[10];
    const float* Wr1 = (const float*)d_in[11];
    const float* br1 = (const float*)d_in[12];
    const float* g1  = (const float*)d_in[13];
    const float* be1 = (const float*)d_in[14];

    const int M = in_sizes[0] / 128;
    const int E = in_sizes[1];

    float *A, *B, *C, *Dd, *stats, *scale, *shift, *W1p, *Wr1p, *c0, *br1p;
    int *rowptr, *cursor, *esrc, *bsum;
    cudaGetSymbolAddress((void**)&A,      g_bufA);
    cudaGetSymbolAddress((void**)&B,      g_bufB);
    cudaGetSymbolAddress((void**)&C,      g_bufC);
    cudaGetSymbolAddress((void**)&Dd,     g_bufD);
    cudaGetSymbolAddress((void**)&stats,  g_stats);
    cudaGetSymbolAddress((void**)&scale,  g_scale);
    cudaGetSymbolAddress((void**)&shift,  g_shift);
    cudaGetSymbolAddress((void**)&W1p,    g_W1p);
    cudaGetSymbolAddress((void**)&Wr1p,   g_Wr1p);
    cudaGetSymbolAddress((void**)&c0,     g_c0);
    cudaGetSymbolAddress((void**)&br1p,   g_br1p);
    cudaGetSymbolAddress((void**)&rowptr, g_rowptr);
    cudaGetSymbolAddress((void**)&cursor, g_cursor);
    cudaGetSymbolAddress((void**)&esrc,   g_esrc);
    cudaGetSymbolAddress((void**)&bsum,   g_bsum);

    const int gBlocks = (M + 127) / 128;
    const int eBlocks = (E + 255) / 256;
    const int nb = (M + 2047) / 2048;
    const int gcBlocks = 1184;   // 148 SMs * 8
    float* out = (float*)d_out;

    // ---- CSR build (deg histogram in `cursor`, then scan into rowptr) ----
    cudaMemsetAsync(cursor, 0, (size_t)M * sizeof(int));
    hist_kernel<<<eBlocks, 256>>>(dst, cursor, E);
    scan1_kernel<<<nb, 256>>>(cursor, rowptr, bsum, M);
    scan2_kernel<<<1, 32>>>(bsum, nb);
    scan3_kernel<<<nb, 256>>>(rowptr, cursor, bsum, M, E);
    fill_kernel<<<eBlocks, 256>>>(src, dst, cursor, esrc, E);

    // ---- Layer 1 ----
    gemm_kernel<<<gBlocks, 256>>>(h, W0, nullptr, A, M, 0);   // m1
    gemm_kernel<<<gBlocks, 256>>>(h, Wr0, br0, B, M, 1);      // res1
    cudaMemsetAsync(stats, 0, 256 * sizeof(float));
    gather_combine_kernel<<<gcBlocks, 256>>>(A, B, b0, nullptr, rowptr, esrc,
                                             C, stats, M);    // y1 -> C
    finalize_kernel<<<1, 128>>>(stats, g0, be0, 1.0f / (float)M, scale, shift);
    // Fold layer-1 BN into layer-2 weights
    fold_w_kernel<<<128, 128>>>(scale, W1, W1p);
    fold_w_kernel<<<128, 128>>>(scale, Wr1, Wr1p);
    fold_bias_kernel<<<1, 128>>>(shift, W1, nullptr, c0);     // c0 = shift @ W1
    fold_bias_kernel<<<1, 128>>>(shift, Wr1, br1, br1p);      // br1p = shift@Wr1 + br1

    // ---- Layer 2 (operates on pre-norm y1; BN folded into weights) ----
    gemm_kernel<<<gBlocks, 256>>>(C, W1p, nullptr, A, M, 0);  // m2' = y1@W1p
    gemm_kernel<<<gBlocks, 256>>>(C, Wr1p, br1p, B, M, 1);    // res2
    cudaMemsetAsync(stats, 0, 256 * sizeof(float));
    gather_combine_kernel<<<gcBlocks, 256>>>(A, B, b1, c0, rowptr, esrc,
                                             Dd, stats, M);   // y2 -> D
    finalize_kernel<<<1, 128>>>(stats, g1, be1, 1.0f / (float)M, scale, shift);
    normalize_kernel<<<1024, 256>>>(Dd, scale, shift, out, M);
}

// round 5
// speedup vs baseline: 1.9801x; 1.4081x over previous
#include <cuda_runtime.h>
#include <cuda_bf16.h>
#include <cstdint>
#include <cstddef>

#define NODES_MAX 100000
#define EDGES_MAX 1600000
#define DD 128

// ---------------------------------------------------------------------------
// Static device scratch
// ---------------------------------------------------------------------------
__device__ float g_bufA[(size_t)NODES_MAX * DD];   // m (x @ W)
__device__ float g_bufB[(size_t)NODES_MAX * DD];   // res
__device__ float g_bufC[(size_t)NODES_MAX * DD];   // y1
__device__ float g_bufD[(size_t)NODES_MAX * DD];   // y2
__device__ float g_stats[2 * DD];
__device__ float g_scale[DD];
__device__ float g_shift[DD];
__device__ float g_c0[DD];
__device__ float g_br1p[DD];
__device__ int   g_rowptr[NODES_MAX + 1];
__device__ int   g_cursor[NODES_MAX];
__device__ int   g_esrc[EDGES_MAX];
__device__ int   g_bsum[128];
// 4 weight images (W0, Wr0, W1p, Wr1p): transposed [n][k] bf16, hi split then
// lo split (each 16384 elems)
__device__ __nv_bfloat16 g_wimg[4][32768];

// ---------------------------------------------------------------------------
// mma.sync / ldmatrix helpers (target-portable PTX, no 'a'-suffix features)
// ---------------------------------------------------------------------------
__device__ __forceinline__ uint32_t smem_to_u32(const void* p) {
    uint32_t a;
    asm("{ .reg .u64 t; cvta.to.shared.u64 t, %1; cvt.u32.u64 %0, t; }"
        : "=r"(a) : "l"(p));
    return a;
}

#define LDSM_X4(r0, r1, r2, r3, addr) \
    asm volatile("ldmatrix.sync.aligned.m8n8.x4.shared.b16 {%0,%1,%2,%3}, [%4];" \
                 : "=r"(r0), "=r"(r1), "=r"(r2), "=r"(r3) : "r"(addr))
#define LDSM_X2(r0, r1, addr) \
    asm volatile("ldmatrix.sync.aligned.m8n8.x2.shared.b16 {%0,%1}, [%2];" \
                 : "=r"(r0), "=r"(r1) : "r"(addr))

__device__ __forceinline__ void mma16816(float* c, const uint32_t* a,
                                         const uint32_t* b) {
    asm volatile(
        "mma.sync.aligned.m16n8k16.row.col.f32.bf16.bf16.f32 "
        "{%0,%1,%2,%3}, {%4,%5,%6,%7}, {%8,%9}, {%0,%1,%2,%3};"
        : "+f"(c[0]), "+f"(c[1]), "+f"(c[2]), "+f"(c[3])
        : "r"(a[0]), "r"(a[1]), "r"(a[2]), "r"(a[3]), "r"(b[0]), "r"(b[1]));
}

// ---------------------------------------------------------------------------
// Weight prep: W fp32 [k][n] (optionally scaled by scale[k]) -> transposed
// [n][k] bf16 hi/lo split images
// ---------------------------------------------------------------------------
__global__ void prep_w_kernel(const float* __restrict__ W,
                              const float* __restrict__ scale,
                              __nv_bfloat16* __restrict__ img)
{
    int n = blockIdx.x;
    int k = threadIdx.x;
    float w = W[k * 128 + n];
    if (scale) w *= scale[k];
    __nv_bfloat16 hi = __float2bfloat16_rn(w);
    img[n * 128 + k] = hi;
    img[16384 + n * 128 + k] = __float2bfloat16_rn(w - __bfloat162float(hi));
}

// ---------------------------------------------------------------------------
// Fused GEMM pair via mma.sync bf16 3-term split:
//   outM = A @ W
//   outR = relu(A @ Wr + br)
// BM=128, 512 threads (16 warps: 2 row-groups x 8 col-groups of 256 cols)
// ---------------------------------------------------------------------------
#define RS      272u          // padded smem row stride (bytes) -> conflict-free ldmatrix
#define SM_AHI  0u
#define SM_ALO  34816u        // 128*272
#define SM_BHI  69632u
#define SM_BLO  139264u       // + 256*272
#define SMEM_GP 208896u       // total

__device__ __forceinline__ void cvt_pair(float a, float b, char* phi, char* plo)
{
    __nv_bfloat16 ha = __float2bfloat16_rn(a);
    __nv_bfloat16 hb = __float2bfloat16_rn(b);
    *(__nv_bfloat162*)phi = __halves2bfloat162(ha, hb);
    *(__nv_bfloat162*)plo = __halves2bfloat162(
        __float2bfloat16_rn(a - __bfloat162float(ha)),
        __float2bfloat16_rn(b - __bfloat162float(hb)));
}

__global__ __launch_bounds__(512, 1) void gemm_pair_kernel(
    const float* __restrict__ A,
    const __nv_bfloat16* __restrict__ imgW,
    const __nv_bfloat16* __restrict__ imgR,
    const float* __restrict__ br,
    float* __restrict__ outM, float* __restrict__ outR, int M)
{
    extern __shared__ char sm[];
    const uint32_t smb = smem_to_u32(sm);
    const int tid = threadIdx.x;
    const int warp = tid >> 5;
    const int lane = tid & 31;
    const int m0 = blockIdx.x * 128;

    // ---- A tile: load fp32, split to bf16 hi/lo (4 threads per row) ----
    // Each thread covers 32 columns = 32 bf16 = 64 bytes per split.
    // One float4 (4 floats) -> 4 bf16 = 8 bytes: stride j*8, halves at +0/+4.
    {
        int r = tid >> 2;
        int c0 = (tid & 3) * 32;
        char* phi = sm + SM_AHI + r * RS + c0 * 2;
        char* plo = sm + SM_ALO + r * RS + c0 * 2;
        int gr = m0 + r;
        if (gr < M) {
            const float4* ap = (const float4*)(A + (size_t)gr * 128 + c0);
#pragma unroll
            for (int j = 0; j < 8; j++) {
                float4 v = ap[j];
                cvt_pair(v.x, v.y, phi + j * 8,     plo + j * 8);
                cvt_pair(v.z, v.w, phi + j * 8 + 4, plo + j * 8 + 4);
            }
        } else {
#pragma unroll
            for (int j = 0; j < 4; j++) {
                *(float4*)(phi + j * 16) = make_float4(0.f, 0.f, 0.f, 0.f);
                *(float4*)(plo + j * 16) = make_float4(0.f, 0.f, 0.f, 0.f);
            }
        }
    }

    // ---- B tiles: copy pre-split images (rows 0-127: W^T, 128-255: Wr^T) ----
    for (int i = tid; i < 4096; i += 512) {
        int row = i >> 4, q = i & 15;
        const __nv_bfloat16* srcb = (row < 128) ? imgW : imgR;
        int r = row & 127;
        uint4 vhi = ((const uint4*)(srcb + r * 128))[q];
        uint4 vlo = ((const uint4*)(srcb + 16384 + r * 128))[q];
        *(uint4*)(sm + SM_BHI + row * RS + q * 16) = vhi;
        *(uint4*)(sm + SM_BLO + row * RS + q * 16) = vlo;
    }
    __syncthreads();

    // ---- Main MMA loop ----
    const int wm = warp >> 3;   // 0..1 : rows [wm*64, +64)
    const int wn = warp & 7;    // 0..7 : cols [wn*32, +32) of 256

    float acc[4][4][4];
#pragma unroll
    for (int mt = 0; mt < 4; mt++)
#pragma unroll
        for (int nt = 0; nt < 4; nt++)
#pragma unroll
            for (int j = 0; j < 4; j++) acc[mt][nt][j] = 0.f;

    const uint32_t a_addr0 = smb + SM_AHI
        + (uint32_t)(wm * 64 + (lane & 15)) * RS + (uint32_t)((lane >> 4) & 1) * 16u;
    const uint32_t b_addr0 = smb + SM_BHI
        + (uint32_t)(wn * 32 + (lane & 7)) * RS + (uint32_t)((lane >> 3) & 1) * 16u;

#pragma unroll
    for (int ks = 0; ks < 8; ks++) {
        const uint32_t koff = (uint32_t)ks * 32u;   // 16 bf16 = 32 bytes
        uint32_t ahi[4][4], bhi[4][2], blo[4][2];
#pragma unroll
        for (int mt = 0; mt < 4; mt++)
            LDSM_X4(ahi[mt][0], ahi[mt][1], ahi[mt][2], ahi[mt][3],
                    a_addr0 + (uint32_t)(mt * 16) * RS + koff);
#pragma unroll
        for (int nt = 0; nt < 4; nt++) {
            uint32_t ba = b_addr0 + (uint32_t)(nt * 8) * RS + koff;
            LDSM_X2(bhi[nt][0], bhi[nt][1], ba);
            LDSM_X2(blo[nt][0], blo[nt][1], ba + (SM_BLO - SM_BHI));
        }
        // hh + hl terms
#pragma unroll
        for (int mt = 0; mt < 4; mt++)
#pragma unroll
            for (int nt = 0; nt < 4; nt++) {
                mma16816(acc[mt][nt], ahi[mt], bhi[nt]);
                mma16816(acc[mt][nt], ahi[mt], blo[nt]);
            }
        // lh term (ahi regs dead -> reused by compiler)
        uint32_t alo[4][4];
#pragma unroll
        for (int mt = 0; mt < 4; mt++)
            LDSM_X4(alo[mt][0], alo[mt][1], alo[mt][2], alo[mt][3],
                    a_addr0 + (SM_ALO - SM_AHI) + (uint32_t)(mt * 16) * RS + koff);
#pragma unroll
        for (int mt = 0; mt < 4; mt++)
#pragma unroll
            for (int nt = 0; nt < 4; nt++)
                mma16816(acc[mt][nt], alo[mt], bhi[nt]);
    }

    // ---- Epilogue ----
    const bool isRes = (wn >= 4);
    const int colb = wn * 32 - (isRes ? 128 : 0);
    float* baseo = isRes ? outR : outM;
#pragma unroll
    for (int mt = 0; mt < 4; mt++) {
        int row0 = m0 + wm * 64 + mt * 16 + (lane >> 2);
#pragma unroll
        for (int nt = 0; nt < 4; nt++) {
            int col = colb + nt * 8 + (lane & 3) * 2;
            float v0 = acc[mt][nt][0], v1 = acc[mt][nt][1];
            float v2 = acc[mt][nt][2], v3 = acc[mt][nt][3];
            if (isRes) {
                float q0 = __ldg(br + col), q1 = __ldg(br + col + 1);
                v0 = fmaxf(v0 + q0, 0.f); v1 = fmaxf(v1 + q1, 0.f);
                v2 = fmaxf(v2 + q0, 0.f); v3 = fmaxf(v3 + q1, 0.f);
            }
            if (row0 < M)
                *(float2*)(baseo + (size_t)row0 * 128 + col) = make_float2(v0, v1);
            if (row0 + 8 < M)
                *(float2*)(baseo + (size_t)(row0 + 8) * 128 + col) = make_float2(v2, v3);
        }
    }
}

// ---------------------------------------------------------------------------
// CSR build
// ---------------------------------------------------------------------------
__global__ void hist_kernel(const int* __restrict__ dst, int* __restrict__ deg, int E)
{
    int i = blockIdx.x * blockDim.x + threadIdx.x;
    if (i < E) atomicAdd(&deg[dst[i]], 1);
}

__global__ void scan1_kernel(const int* __restrict__ deg, int* __restrict__ rowptr,
                             int* __restrict__ bsum, int N)
{
    __shared__ int ws[8];
    int tid = threadIdx.x;
    int base = blockIdx.x * 2048 + tid * 8;
    int v[8];
    int run = 0;
#pragma unroll
    for (int i = 0; i < 8; i++) {
        int t = (base + i < N) ? deg[base + i] : 0;
        v[i] = run;
        run += t;
    }
    int lane = tid & 31, wid = tid >> 5;
    int x = run;
#pragma unroll
    for (int o = 1; o < 32; o <<= 1) {
        int y = __shfl_up_sync(0xffffffffu, x, o);
        if (lane >= o) x += y;
    }
    if (lane == 31) ws[wid] = x;
    __syncthreads();
    if (tid == 0) {
        int acc = 0;
#pragma unroll
        for (int j = 0; j < 8; j++) { int t = ws[j]; ws[j] = acc; acc += t; }
        bsum[blockIdx.x] = acc;
    }
    __syncthreads();
    int excl = x - run + ws[wid];
#pragma unroll
    for (int i = 0; i < 8; i++)
        if (base + i < N) rowptr[base + i] = excl + v[i];
}

__global__ void scan2_kernel(int* __restrict__ bsum, int nb)
{
    if (threadIdx.x == 0) {
        int acc = 0;
        for (int b = 0; b < nb; b++) { int t = bsum[b]; bsum[b] = acc; acc += t; }
    }
}

__global__ void scan3_kernel(int* __restrict__ rowptr, int* __restrict__ cursor,
                             const int* __restrict__ bsum, int N, int E)
{
    int base = blockIdx.x * 2048 + threadIdx.x * 8;
    int off = bsum[blockIdx.x];
#pragma unroll
    for (int k = 0; k < 8; k++) {
        int idx = base + k;
        if (idx < N) {
            int r = rowptr[idx] + off;
            rowptr[idx] = r;
            cursor[idx] = r;
        }
    }
    if (blockIdx.x == 0 && threadIdx.x == 0) rowptr[N] = E;
}

__global__ void fill_kernel(const int* __restrict__ src, const int* __restrict__ dst,
                            int* __restrict__ cursor, int* __restrict__ esrc, int E)
{
    int i = blockIdx.x * blockDim.x + threadIdx.x;
    if (i < E) {
        int p = atomicAdd(&cursor[dst[i]], 1);
        esrc[p] = src[i];
    }
}

// ---------------------------------------------------------------------------
// Fused gather + combine + stats
// ---------------------------------------------------------------------------
__global__ __launch_bounds__(256) void gather_combine_kernel(
    const float* __restrict__ m, const float* __restrict__ res,
    const float* __restrict__ bias, const float* __restrict__ c0,
    const int* __restrict__ rowptr, const int* __restrict__ esrc,
    float* __restrict__ out, float* __restrict__ stats, int M)
{
    const int lane = threadIdx.x & 31;
    const int wid  = threadIdx.x >> 5;
    const int nwarps = (gridDim.x * blockDim.x) >> 5;
    const int w0 = (blockIdx.x * blockDim.x + threadIdx.x) >> 5;

    float4 b4 = ((const float4*)bias)[lane];
    float4 c04 = make_float4(0.f, 0.f, 0.f, 0.f);
    if (c0) c04 = ((const float4*)c0)[lane];

    float4 s = make_float4(0.f, 0.f, 0.f, 0.f);
    float4 q = make_float4(0.f, 0.f, 0.f, 0.f);

    for (int node = w0; node < M; node += nwarps) {
        int start = rowptr[node], end = rowptr[node + 1];
        float4 a0 = make_float4(0.f, 0.f, 0.f, 0.f);
        float4 a1 = make_float4(0.f, 0.f, 0.f, 0.f);
        int e = start;
        for (; e + 1 < end; e += 2) {
            int s0 = __ldg(esrc + e);
            int s1 = __ldg(esrc + e + 1);
            float4 v0 = ((const float4*)(m + (size_t)s0 * 128))[lane];
            float4 v1 = ((const float4*)(m + (size_t)s1 * 128))[lane];
            a0.x += v0.x; a0.y += v0.y; a0.z += v0.z; a0.w += v0.w;
            a1.x += v1.x; a1.y += v1.y; a1.z += v1.z; a1.w += v1.w;
        }
        if (e < end) {
            int s0 = __ldg(esrc + e);
            float4 v0 = ((const float4*)(m + (size_t)s0 * 128))[lane];
            a0.x += v0.x; a0.y += v0.y; a0.z += v0.z; a0.w += v0.w;
        }
        float deg = (float)(end - start);
        float4 rr = ((const float4*)(res + (size_t)node * 128))[lane];
        float4 v;
        v.x = fmaxf(a0.x + a1.x + b4.x + deg * c04.x, 0.f) + rr.x;
        v.y = fmaxf(a0.y + a1.y + b4.y + deg * c04.y, 0.f) + rr.y;
        v.z = fmaxf(a0.z + a1.z + b4.z + deg * c04.z, 0.f) + rr.z;
        v.w = fmaxf(a0.w + a1.w + b4.w + deg * c04.w, 0.f) + rr.w;
        ((float4*)(out + (size_t)node * 128))[lane] = v;
        s.x += v.x; s.y += v.y; s.z += v.z; s.w += v.w;
        q.x += v.x * v.x; q.y += v.y * v.y; q.z += v.z * v.z; q.w += v.w * v.w;
    }

    __shared__ float4 sh[8][32];
    __shared__ float4 shq[8][32];
    sh[wid][lane] = s;
    shq[wid][lane] = q;
    __syncthreads();

    if (wid == 0) {
#pragma unroll
        for (int j = 1; j < 8; j++) {
            float4 t = sh[j][lane];
            s.x += t.x; s.y += t.y; s.z += t.z; s.w += t.w;
            float4 u = shq[j][lane];
            q.x += u.x; q.y += u.y; q.z += u.z; q.w += u.w;
        }
        atomicAdd(&stats[lane * 4 + 0], s.x);
        atomicAdd(&stats[lane * 4 + 1], s.y);
        atomicAdd(&stats[lane * 4 + 2], s.z);
        atomicAdd(&stats[lane * 4 + 3], s.w);
        atomicAdd(&stats[128 + lane * 4 + 0], q.x);
        atomicAdd(&stats[128 + lane * 4 + 1], q.y);
        atomicAdd(&stats[128 + lane * 4 + 2], q.z);
        atomicAdd(&stats[128 + lane * 4 + 3], q.w);
    }
}

// ---------------------------------------------------------------------------
// BN finalize + bias folding + normalize
// ---------------------------------------------------------------------------
__global__ void finalize_kernel(const float* __restrict__ stats,
                                const float* __restrict__ g,
                                const float* __restrict__ be,
                                float invN,
                                float* __restrict__ scale,
                                float* __restrict__ shift)
{
    int j = threadIdx.x;
    float mu = stats[j] * invN;
    float var = stats[128 + j] * invN - mu * mu;
    float sc = rsqrtf(var + 1e-5f) * g[j];
    scale[j] = sc;
    shift[j] = be[j] - mu * sc;
}

__global__ void fold_bias_kernel(const float* __restrict__ sf,
                                 const float* __restrict__ W,
                                 const float* __restrict__ baseb,
                                 float* __restrict__ outb)
{
    int j = threadIdx.x;
    float s = baseb ? baseb[j] : 0.f;
    for (int k = 0; k < 128; k++) s += sf[k] * W[k * 128 + j];
    outb[j] = s;
}

__global__ __launch_bounds__(256) void normalize_kernel(
    const float* __restrict__ x, const float* __restrict__ scale,
    const float* __restrict__ shift, float* __restrict__ y, int M)
{
    int total = M * 32;
    for (int idx = blockIdx.x * blockDim.x + threadIdx.x; idx < total;
         idx += gridDim.x * blockDim.x) {
        int c4 = idx & 31;
        float4 sc = ((const float4*)scale)[c4];
        float4 sf = ((const float4*)shift)[c4];
        float4 v = ((const float4*)x)[idx];
        v.x = v.x * sc.x + sf.x;
        v.y = v.y * sc.y + sf.y;
        v.z = v.z * sc.z + sf.z;
        v.w = v.w * sc.w + sf.w;
        ((float4*)y)[idx] = v;
    }
}

// ---------------------------------------------------------------------------
extern "C" void kernel_launch(void* const* d_in, const int* in_sizes, int n_in,
                              void* d_out, int out_size)
{
    const float* h   = (const float*)d_in[0];
    const int*   src = (const int*)d_in[1];
    const int*   dst = (const int*)d_in[2];
    const float* W0  = (const float*)d_in[3];
    const float* b0  = (const float*)d_in[4];
    const float* Wr0 = (const float*)d_in[5];
    const float* br0 = (const float*)d_in[6];
    const float* g0  = (const float*)d_in[7];
    const float* be0 = (const float*)d_in[8];
    const float* W1  = (const float*)d_in[9];
    const float* b1  = (const float*)d_in[10];
    const float* Wr1 = (const float*)d_in[11];
    const float* br1 = (const float*)d_in[12];
    const float* g1  = (const float*)d_in[13];
    const float* be1 = (const float*)d_in[14];

    const int M = in_sizes[0] / 128;
    const int E = in_sizes[1];

    float *A, *B, *C, *Dd, *stats, *scale, *shift, *c0, *br1p;
    __nv_bfloat16* wimg;
    int *rowptr, *cursor, *esrc, *bsum;
    cudaGetSymbolAddress((void**)&A,      g_bufA);
    cudaGetSymbolAddress((void**)&B,      g_bufB);
    cudaGetSymbolAddress((void**)&C,      g_bufC);
    cudaGetSymbolAddress((void**)&Dd,     g_bufD);
    cudaGetSymbolAddress((void**)&stats,  g_stats);
    cudaGetSymbolAddress((void**)&scale,  g_scale);
    cudaGetSymbolAddress((void**)&shift,  g_shift);
    cudaGetSymbolAddress((void**)&c0,     g_c0);
    cudaGetSymbolAddress((void**)&br1p,   g_br1p);
    cudaGetSymbolAddress((void**)&rowptr, g_rowptr);
    cudaGetSymbolAddress((void**)&cursor, g_cursor);
    cudaGetSymbolAddress((void**)&esrc,   g_esrc);
    cudaGetSymbolAddress((void**)&bsum,   g_bsum);
    cudaGetSymbolAddress((void**)&wimg,   g_wimg);

    cudaFuncSetAttribute(gemm_pair_kernel,
                         cudaFuncAttributeMaxDynamicSharedMemorySize, SMEM_GP);

    const int eBlocks = (E + 255) / 256;
    const int nb = (M + 2047) / 2048;
    const int tBlocks = (M + 127) / 128;
    const int gcBlocks = 1184;
    float* out = (float*)d_out;

    // ---- CSR build ----
    cudaMemsetAsync(cursor, 0, (size_t)M * sizeof(int));
    hist_kernel<<<eBlocks, 256>>>(dst, cursor, E);
    scan1_kernel<<<nb, 256>>>(cursor, rowptr, bsum, M);
    scan2_kernel<<<1, 32>>>(bsum, nb);
    scan3_kernel<<<nb, 256>>>(rowptr, cursor, bsum, M, E);
    fill_kernel<<<eBlocks, 256>>>(src, dst, cursor, esrc, E);

    // ---- Weight prep for layer 1 ----
    prep_w_kernel<<<128, 128>>>(W0, nullptr, wimg + 0 * 32768);
    prep_w_kernel<<<128, 128>>>(Wr0, nullptr, wimg + 1 * 32768);

    // ---- Layer 1 ----
    gemm_pair_kernel<<<tBlocks, 512, SMEM_GP>>>(h, wimg + 0 * 32768,
                                                wimg + 1 * 32768, br0, A, B, M);
    cudaMemsetAsync(stats, 0, 256 * sizeof(float));
    gather_combine_kernel<<<gcBlocks, 256>>>(A, B, b0, nullptr, rowptr, esrc,
                                             C, stats, M);
    finalize_kernel<<<1, 128>>>(stats, g0, be0, 1.0f / (float)M, scale, shift);

    // ---- Fold BN into layer-2 weights during prep ----
    prep_w_kernel<<<128, 128>>>(W1, scale, wimg + 2 * 32768);
    prep_w_kernel<<<128, 128>>>(Wr1, scale, wimg + 3 * 32768);
    fold_bias_kernel<<<1, 128>>>(shift, W1, nullptr, c0);
    fold_bias_kernel<<<1, 128>>>(shift, Wr1, br1, br1p);

    // ---- Layer 2 ----
    gemm_pair_kernel<<<tBlocks, 512, SMEM_GP>>>(C, wimg + 2 * 32768,
                                                wimg + 3 * 32768, br1p, A, B, M);
    cudaMemsetAsync(stats, 0, 256 * sizeof(float));
    gather_combine_kernel<<<gcBlocks, 256>>>(A, B, b1, c0, rowptr, esrc,
                                             Dd, stats, M);
    finalize_kernel<<<1, 128>>>(stats, g1, be1, 1.0f / (float)M, scale, shift);
    normalize_kernel<<<1024, 256>>>(Dd, scale, shift, out, M);
}